// round 17
// baseline (speedup 1.0000x reference)
#include <cuda_runtime.h>
#include <cstdint>

#define LDD 192
#define M_TOTAL 64000
#define AB_STRIDE ((size_t)M_TOTAL * LDD)
#define A0_LD 128
#define GSTRIDE (LDD * LDD)

// ---------------- scratch (static device globals) ----------------
static __device__ float g_B[3 * AB_STRIDE];   // ~147 MB (branch-batched)
static __device__ float g_A[(size_t)M_TOTAL * A0_LD];  // ~33 MB base atlas unfold (branch-shared)
static __device__ float g_G[3 * GSTRIDE];     // G0 per branch: 121 x D
static __device__ float g_T[3 * GSTRIDE];
static __device__ float g_Pt[3 * GSTRIDE];
static __device__ float g_Wp[3 * GSTRIDE];

// ---------------- per-branch compile-time traits ----------------
template<int BR> struct Tr;
template<> struct Tr<0> { // axi
  static constexpr int w0=5,w1=7,w2=4,d=140;
  static constexpr int s0=48,s1=66,s2=38;
  static constexpr int pb0=1,pb1=2,pb2=1;
  static constexpr long OFF=0;
};
template<> struct Tr<1> { // cor (internal transpose 0,1,2,4,3)
  static constexpr int w0=4,w1=4,w2=7,d=112;
  static constexpr int s0=38,s1=38,s2=66;
  static constexpr int pb0=1,pb1=1,pb2=2;
  static constexpr long OFF=7704576;
};
template<> struct Tr<2> { // sag (internal transpose 0,1,4,3,2)
  static constexpr int w0=4,w1=8,w2=5,d=160;
  static constexpr int s0=38,s1=78,s2=48;
  static constexpr int pb0=1,pb1=1,pb2=1;
  static constexpr long OFF=13804032;
};

// branch col -> base atlas unfold col
__device__ __forceinline__ int rowmap(int br, int r, int d) {
  if (r == d) return 120;  // ones column
  const int w1t[3] = {7, 4, 8}, w2t[3] = {4, 7, 5};
  int w1 = w1t[br], w2 = w2t[br];
  int x = r / (w1 * w2), y = (r / w2) % w1, z = r % w2;
  int xb, yb, zb;
  if (br == 0)      { xb = x; yb = (y * 6) / 7; zb = z; }
  else if (br == 1) { int x2=(x*5)/4, y2=(y*7)/4, z2=(z*4)/7; xb=x2; yb=(y2*6)/7; zb=z2; }
  else              { int y3=y/2, z3=(z*7)/5; int x2=(x*5)/4, y2=(y3*7)/4, z2=(z3*4)/7;
                      xb=x2; yb=(y2*6)/7; zb=z2; }
  return (xb * 6 + yb) * 4 + zb;
}

// ---------------- pack: B-hat (3 branches) + A0 + zero G/Wp, ONE launch ----------------
template<int BR>
__device__ void packB_body(const float* __restrict__ feat) {
  constexpr int w0=Tr<BR>::w0, w1=Tr<BR>::w1, w2=Tr<BR>::w2, d=Tr<BR>::d;
  constexpr int s0=Tr<BR>::s0, s1=Tr<BR>::s1, s2=Tr<BR>::s2;
  constexpr int pb0=Tr<BR>::pb0, pb1=Tr<BR>::pb1, pb2=Tr<BR>::pb2;
  float* Bdst = g_B + (size_t)BR * AB_STRIDE;
  int blk = blockIdx.x;
  int c = blk / 100;
  int a = (blk / 10) % 10;
  int b = blk % 10;
  for (int t = threadIdx.x; t < 10 * LDD; t += blockDim.x) {
    int cc = t / LDD;
    int j  = t - cc * LDD;
    int row = blk * 10 + cc;
    float vB;
    if (j < d) {
      int x = j / (w1 * w2);
      int y = (j / w2) % w1;
      int z = j % w2;
      int i0 = a * w0 + x - pb0;
      int i1 = b * w1 + y - pb1;
      int i2 = cc * w2 + z - pb2;
      vB = 0.f;
      if ((unsigned)i0 < (unsigned)s0 && (unsigned)i1 < (unsigned)s1 && (unsigned)i2 < (unsigned)s2) {
        int src;
        if (BR == 0)      src = ((c * 48 + i0) * 66 + i1) * 38 + i2;
        else if (BR == 1) src = ((c * 38 + i0) * 66 + i2) * 38 + i1;
        else              src = ((c * 48 + i2) * 78 + i1) * 38 + i0;
        vB = feat[src];
      }
    } else {
      vB = (j == d) ? 1.f : 0.f;
    }
    Bdst[(size_t)row * LDD + j] = vB;
  }
}

__device__ void packA0_body(const float* __restrict__ atlas) {
  int blk = blockIdx.x;
  int c = blk / 100;
  int a = (blk / 10) % 10;
  int b = blk % 10;
  for (int t = threadIdx.x; t < 10 * A0_LD; t += blockDim.x) {
    int cc = t / A0_LD;
    int j  = t - cc * A0_LD;
    int row = blk * 10 + cc;
    float vA;
    if (j < 120) {
      int x = j / 24;          // w = (5,6,4)
      int y = (j / 4) % 6;
      int z = j % 4;
      int j0 = a * 5 + x - 2;  // atlas aw=(5,6,4), pb=(2,2,1)
      int j1 = b * 6 + y - 2;
      int j2 = cc * 4 + z - 1;
      vA = 0.f;
      if ((unsigned)j0 < 46u && (unsigned)j1 < 56u && (unsigned)j2 < 38u)
        vA = atlas[((c * 46 + j0) * 56 + j1) * 38 + j2];
    } else {
      vA = (j == 120) ? 1.f : 0.f;
    }
    g_A[(size_t)row * A0_LD + j] = vA;
  }
}

__global__ void pack_all(const float* __restrict__ axi, const float* __restrict__ cor,
                         const float* __restrict__ sag, const float* __restrict__ atlas) {
  size_t gid = ((size_t)blockIdx.y * gridDim.x + blockIdx.x) * blockDim.x + threadIdx.x;
  if (gid < (size_t)3 * GSTRIDE) { g_G[gid] = 0.f; g_Wp[gid] = 0.f; }
  if (blockIdx.y == 0)      packB_body<0>(axi);
  else if (blockIdx.y == 1) packB_body<1>(cor);
  else if (blockIdx.y == 2) packB_body<2>(sag);
  else                      packA0_body(atlas);
}

// ---------------- GEMM1 (fused): G0 = A0^T B-hat, p-tile 64x2, q-tile TQ ----------------
template<int BR, int TQ>
__device__ __forceinline__ void g1body(int ms) {
  constexpr int QI = TQ / 8;
  int p0 = blockIdx.x * 64;
  int q0 = blockIdx.y * TQ;
  int m0 = ms * 512;
  int mHi = m0 + 512;
  const float* A  = g_A;
  const float* Bp = g_B + (size_t)BR * AB_STRIDE;
  float* G = g_G + BR * GSTRIDE;
  __shared__ alignas(16) float As[16][64];
  __shared__ alignas(16) float Bs[16][TQ];
  float acc[8][QI] = {};
  int t = threadIdx.x;               // 64 threads
  int tx = t & 7, ty = t >> 3;
  int lr = t >> 2;                   // 16 rows
  int lp = t & 3;                    // 4 threads per row
  float4 pa[4];
  float2 pb[QI];
#define G1_LD(MB)                                                          \
  {                                                                        \
    const float* ar  = A  + (size_t)((MB) + lr) * A0_LD + p0;              \
    const float* brr = Bp + (size_t)((MB) + lr) * LDD + q0;                \
    _Pragma("unroll")                                                      \
    for (int i = 0; i < 4; i++)  pa[i] = *(const float4*)(ar + lp * 16 + i * 4); \
    _Pragma("unroll")                                                      \
    for (int i = 0; i < QI; i++) pb[i] = *(const float2*)(brr + (lp * QI + i) * 2); \
  }
  G1_LD(m0);
  for (int mb = m0; mb < mHi; mb += 16) {
    __syncthreads();
#pragma unroll
    for (int i = 0; i < 4; i++)  *(float4*)&As[lr][lp * 16 + i * 4] = pa[i];
#pragma unroll
    for (int i = 0; i < QI; i++) *(float2*)&Bs[lr][(lp * QI + i) * 2] = pb[i];
    __syncthreads();
    if (mb + 16 < mHi) G1_LD(mb + 16);
#pragma unroll
    for (int k = 0; k < 16; k++) {
      float a[8], b[QI];
      *(float4*)&a[0] = *(float4*)&As[k][ty * 8];
      *(float4*)&a[4] = *(float4*)&As[k][ty * 8 + 4];
      if (QI % 2 == 0) {
#pragma unroll
        for (int j = 0; j < QI / 2; j++) {
          float2 vb = *(float2*)&Bs[k][tx * QI + 2 * j];
          b[2 * j] = vb.x; b[2 * j + 1] = vb.y;
        }
      } else {
#pragma unroll
        for (int j = 0; j < QI; j++) b[j] = Bs[k][tx * QI + j];
      }
#pragma unroll
      for (int i = 0; i < 8; i++)
#pragma unroll
        for (int j = 0; j < QI; j++)
          acc[i][j] += a[i] * b[j];
    }
  }
#pragma unroll
  for (int i = 0; i < 8; i++)
#pragma unroll
    for (int j = 0; j < QI; j++)
      atomicAdd(&G[(p0 + ty * 8 + i) * LDD + q0 + tx * QI + j], acc[i][j]);
#undef G1_LD
}

// grid: x=2 (p tiles of 64 covering 121), y=3 (q tiles; br1 masks y<2), z=375 (branch*125 + split)
__global__ void __launch_bounds__(64, 8) gemm1_all() {
  int z = blockIdx.z;
  int br = z / 125;
  int ms = z - br * 125;
  if (br == 0)      { g1body<0, 48>(ms); }
  else if (br == 1) { if (blockIdx.y < 2) g1body<1, 64>(ms); }
  else              { g1body<2, 56>(ms); }
}

// ---------------- small chain (batched across branches, 4 rows/block) ----------------
struct P3 { const float* W0; const float* b0; const float* W1; const float* b1;
            const float* W2; const float* b2; };

__device__ __forceinline__ void sel(const P3& p, int br, const float*& W, const float*& b) {
  if (br == 0)      { W = p.W0; b = p.b0; }
  else if (br == 1) { W = p.W1; b = p.b1; }
  else              { W = p.W2; b = p.b2; }
}

// T rows rb..rb+3 = G-hat rows @ Wk-hat
__global__ void k3a_all(P3 pk) {
  const int dTab[3] = {140, 112, 160};
  int br = blockIdx.x / 41;
  int rb = (blockIdx.x - br * 41) * 4;
  int d = dTab[br];
  if (rb > d) return;
  const float *Wk, *bk; sel(pk, br, Wk, bk);
  const float* G = g_G + br * GSTRIDE;
  float* T = g_T + br * GSTRIDE;
  __shared__ float gsh[4][192];
  int t = threadIdx.x;               // 192
#pragma unroll
  for (int q = 0; q < 4; q++) {
    int r = rb + q;
    gsh[q][t] = (r <= d && t <= d) ? G[rowmap(br, r, d) * LDD + t] : 0.f;
  }
  __syncthreads();
  if (t < d) {
    float s[4];
    float bv = bk[t];
#pragma unroll
    for (int q = 0; q < 4; q++) s[q] = gsh[q][d] * bv;
    for (int ss = 0; ss < d; ss++) {
      float w = Wk[ss * d + t];
#pragma unroll
      for (int q = 0; q < 4; q++) s[q] += gsh[q][ss] * w;
    }
#pragma unroll
    for (int q = 0; q < 4; q++)
      if (rb + q <= d) T[(rb + q) * LDD + t] = s[q];
  }
}

// S rows pb..pb+3 = Wq-hat[:,p]^T @ T, fused softmax (4 rows reduced together), write Pt
__global__ void k3b_all(P3 pq) {
  const int dTab[3] = {140, 112, 160};
  int br = blockIdx.x / 40;
  int p4 = (blockIdx.x - br * 40) * 4;
  int d = dTab[br];
  if (p4 >= d) return;
  const float *Wq, *bq; sel(pq, br, Wq, bq);
  const float* T = g_T + br * GSTRIDE;
  float* Pt = g_Pt + br * GSTRIDE;
  __shared__ float wq[4][192];
  __shared__ float red[4][256];
  int t = threadIdx.x;               // 256
  int D = d + 1;
  if (t < 192) {
#pragma unroll
    for (int q = 0; q < 4; q++) {
      int p = p4 + q;
      wq[q][t] = (p < d) ? ((t < d) ? Wq[t * d + p] : ((t == d) ? bq[p] : 0.f)) : 0.f;
    }
  }
  __syncthreads();
  float s[4] = {0.f, 0.f, 0.f, 0.f};
  if (t < d) {
    for (int r = 0; r < D; r++) {
      float tv = T[r * LDD + t];
#pragma unroll
      for (int q = 0; q < 4; q++) s[q] += wq[q][r] * tv;
    }
  }
  // 4-row max reduction
#pragma unroll
  for (int q = 0; q < 4; q++) red[q][t] = (t < d) ? s[q] : -3.0e38f;
  __syncthreads();
  for (int o = 128; o > 0; o >>= 1) {
    if (t < o) {
#pragma unroll
      for (int q = 0; q < 4; q++) red[q][t] = fmaxf(red[q][t], red[q][t + o]);
    }
    __syncthreads();
  }
  float mx[4];
#pragma unroll
  for (int q = 0; q < 4; q++) mx[q] = red[0 + q][0];
  __syncthreads();
  float e[4];
#pragma unroll
  for (int q = 0; q < 4; q++) {
    e[q] = (t < d) ? expf(s[q] - mx[q]) : 0.f;
    red[q][t] = e[q];
  }
  __syncthreads();
  for (int o = 128; o > 0; o >>= 1) {
    if (t < o) {
#pragma unroll
      for (int q = 0; q < 4; q++) red[q][t] += red[q][t + o];
    }
    __syncthreads();
  }
  if (t < d) {
#pragma unroll
    for (int q = 0; q < 4; q++) {
      int p = p4 + q;
      if (p < d) Pt[t * LDD + p] = e[q] / red[q][0];
    }
  }
}

// W' rows jb..jb+3 = Wv-hat[j,:] @ P^T
__global__ void k3d_all(P3 pv) {
  const int dTab[3] = {140, 112, 160};
  int br = blockIdx.x / 41;
  int jb = (blockIdx.x - br * 41) * 4;
  int d = dTab[br];
  if (jb > d) return;
  const float *Wv, *bv; sel(pv, br, Wv, bv);
  const float* Pt = g_Pt + br * GSTRIDE;
  float* Wp = g_Wp + br * GSTRIDE;
  __shared__ float wv[4][192];
  int t = threadIdx.x;               // 192
#pragma unroll
  for (int q = 0; q < 4; q++) {
    int j = jb + q;
    wv[q][t] = (j <= d && t < d) ? ((j < d) ? Wv[j * d + t] : bv[t]) : 0.f;
  }
  __syncthreads();
  if (t < d) {
    float s[4] = {0.f, 0.f, 0.f, 0.f};
    for (int l = 0; l < d; l++) {
      float pvv = Pt[l * LDD + t];
#pragma unroll
      for (int q = 0; q < 4; q++) s[q] += wv[q][l] * pvv;
    }
#pragma unroll
    for (int q = 0; q < 4; q++)
      if (jb + q <= d) Wp[(jb + q) * LDD + t] = s[q];
  }
}

// ---------------- GEMM2: cross = B-hat @ W', 128 x TN tile (TN=48/56/56), fused scatter ----------------
template<int BR, int TN>
__device__ __forceinline__ void gemm2_body(float* __restrict__ out) {
  constexpr int d  = Tr<BR>::d;
  constexpr int w0 = Tr<BR>::w0, w1 = Tr<BR>::w1, w2 = Tr<BR>::w2;
  constexpr int s0 = Tr<BR>::s0, s1 = Tr<BR>::s1, s2 = Tr<BR>::s2;
  constexpr int pb0 = Tr<BR>::pb0, pb1 = Tr<BR>::pb1, pb2 = Tr<BR>::pb2;
  constexpr int KK = ((d + 1 + 15) / 16) * 16;
  constexpr int TNI = TN / 8;
  constexpr int WPT = (16 * TN) / 128;
  int m0 = blockIdx.x * 128;
  int n0 = blockIdx.y * TN;
  const float* Bg = g_B + (size_t)BR * AB_STRIDE;
  const float* Wp = g_Wp + BR * GSTRIDE;
  __shared__ alignas(16) float Bs[16][128];    // transposed: Bs[k][m]
  __shared__ alignas(16) float Ws[16][TN];
  float acc[8][TNI] = {};
  int t = threadIdx.x;               // 128 threads
  int tx = t & 7, ty = t >> 3;
  int wk[WPT], wn[WPT];
#pragma unroll
  for (int j = 0; j < WPT; j++) {
    int i = t + j * 128;
    wk[j] = i / TN;
    wn[j] = i - wk[j] * TN;
  }
  float4 pbv[4];
  float pw[WPT];
#define G2_LD(K0)                                                          \
  {                                                                        \
    _Pragma("unroll")                                                      \
    for (int jj = 0; jj < 4; jj++)                                         \
      pbv[jj] = *(const float4*)(Bg + (size_t)(m0 + t) * LDD + (K0) + jj * 4); \
    _Pragma("unroll")                                                      \
    for (int jj = 0; jj < WPT; jj++)                                       \
      pw[jj] = Wp[(size_t)((K0) + wk[jj]) * LDD + n0 + wn[jj]];            \
  }
  G2_LD(0);
  for (int k0 = 0; k0 < KK; k0 += 16) {
    __syncthreads();
#pragma unroll
    for (int jj = 0; jj < 4; jj++) {
      Bs[jj * 4 + 0][t] = pbv[jj].x;
      Bs[jj * 4 + 1][t] = pbv[jj].y;
      Bs[jj * 4 + 2][t] = pbv[jj].z;
      Bs[jj * 4 + 3][t] = pbv[jj].w;
    }
#pragma unroll
    for (int jj = 0; jj < WPT; jj++)
      Ws[wk[jj]][wn[jj]] = pw[jj];
    __syncthreads();
    if (k0 + 16 < KK) G2_LD(k0 + 16);
#pragma unroll
    for (int k = 0; k < 16; k++) {
      float a[8], b[TNI];
      *(float4*)&a[0] = *(float4*)&Bs[k][ty * 8];
      *(float4*)&a[4] = *(float4*)&Bs[k][ty * 8 + 4];
      if (TNI % 2 == 0) {
#pragma unroll
        for (int j = 0; j < TNI / 2; j++) {
          float2 vb = *(float2*)&Ws[k][tx * TNI + 2 * j];
          b[2 * j] = vb.x; b[2 * j + 1] = vb.y;
        }
      } else {
#pragma unroll
        for (int j = 0; j < TNI; j++) b[j] = Ws[k][tx * TNI + j];
      }
#pragma unroll
      for (int i = 0; i < 8; i++)
#pragma unroll
        for (int j = 0; j < TNI; j++)
          acc[i][j] += a[i] * b[j];
    }
  }
#undef G2_LD
  int rc[8], ra[8], rb[8], rcc[8];
#pragma unroll
  for (int i = 0; i < 8; i++) {
    int m = m0 + ty * 8 + i;
    int c = m / 1000;
    int rem = m - c * 1000;
    rc[i]  = c;
    ra[i]  = (rem / 100) * w0 - pb0;
    rb[i]  = ((rem / 10) % 10) * w1 - pb1;
    rcc[i] = (rem % 10) * w2 - pb2;
  }
  int cx[TNI], cy[TNI], cz[TNI]; bool cok[TNI];
#pragma unroll
  for (int j = 0; j < TNI; j++) {
    int col = n0 + tx * TNI + j;
    cok[j] = col < d;
    cx[j] = col / (w1 * w2);
    cy[j] = (col / w2) % w1;
    cz[j] = col % w2;
  }
#pragma unroll
  for (int i = 0; i < 8; i++) {
#pragma unroll
    for (int j = 0; j < TNI; j++) {
      if (cok[j]) {
        int u0 = ra[i] + cx[j];
        int u1 = rb[i] + cy[j];
        int u2 = rcc[i] + cz[j];
        if ((unsigned)u0 < (unsigned)s0 && (unsigned)u1 < (unsigned)s1 && (unsigned)u2 < (unsigned)s2) {
          long dst;
          if (BR == 0)      dst = ((long)(rc[i] * 48 + u0) * 66 + u1) * 38 + u2;
          else if (BR == 1) dst = ((long)(rc[i] * 38 + u0) * 66 + u2) * 38 + u1;
          else              dst = ((long)(rc[i] * 48 + u2) * 78 + u1) * 38 + u0;
          out[Tr<BR>::OFF + dst] = acc[i][j];
        }
      }
    }
  }
}

__global__ void __launch_bounds__(128, 4) gemm2_all(float* __restrict__ out) {
  if (blockIdx.z == 0)      { gemm2_body<0, 48>(out); }
  else if (blockIdx.z == 1) { if (blockIdx.y < 2) gemm2_body<1, 56>(out); }
  else                      { gemm2_body<2, 56>(out); }
}

// ---------------- host driver ----------------
extern "C" void kernel_launch(void* const* d_in, const int* in_sizes, int n_in,
                              void* d_out, int out_size) {
  const float* axi   = (const float*)d_in[0];
  const float* cor   = (const float*)d_in[1];
  const float* sag   = (const float*)d_in[2];
  const float* atlas = (const float*)d_in[3];
  float* out = (float*)d_out;

  P3 pq = { (const float*)d_in[4],  (const float*)d_in[5],
            (const float*)d_in[10], (const float*)d_in[11],
            (const float*)d_in[16], (const float*)d_in[17] };
  P3 pk = { (const float*)d_in[6],  (const float*)d_in[7],
            (const float*)d_in[12], (const float*)d_in[13],
            (const float*)d_in[18], (const float*)d_in[19] };
  P3 pv = { (const float*)d_in[8],  (const float*)d_in[9],
            (const float*)d_in[14], (const float*)d_in[15],
            (const float*)d_in[20], (const float*)d_in[21] };

  pack_all<<<dim3(6400, 4), 256>>>(axi, cor, sag, atlas);  // B x3 + A0 + zero G/Wp
  gemm1_all<<<dim3(2, 3, 375), 64>>>();
  k3a_all<<<3 * 41, 192>>>(pk);
  k3b_all<<<3 * 40, 256>>>(pq);
  k3d_all<<<3 * 41, 192>>>(pv);
  gemm2_all<<<dim3(500, 3, 3), 128>>>(out);
}